// round 1
// baseline (speedup 1.0000x reference)
#include <cuda_runtime.h>
#include <cuda_bf16.h>

// Problem constants
#define B_   2
#define INC_ 64
#define OUTC_ 128
#define NP_  8
#define D_   12
#define H_   48
#define W_   48
#define HW_   (H_*W_)        // 2304
#define DHW_  (D_*HW_)       // 27648
#define OFFC_ (3*NP_)        // 24
#define REDN_ (B_*DHW_)      // 55296 elements per channel for BN

// Scratch (no allocations allowed -> device globals)
__device__ float g_offset[B_*OFFC_*DHW_];   // 1,327,104 floats (~5.3 MB)
__device__ float g_out[B_*OUTC_*DHW_];      // 7,077,888 floats (~28.3 MB)
__device__ float g_wt[INC_*NP_*OUTC_];      // w_conv transposed to [c][n][o]
__device__ float g_mean[OUTC_];
__device__ float g_rstd[OUTC_];

// _p_n(8) tables: base=3, dep=2, row=1, mod=2
__device__ __constant__ float c_pnz[8] = {0,0,0,1,1,1,2,2};
__device__ __constant__ float c_pnx[8] = {0,0,0,0,0,0,1,1};
__device__ __constant__ float c_pny[8] = {0,1,2,0,1,2,0,1};

// ---------------------------------------------------------------------------
// Kernel 0: transpose w_conv [o][c][n] -> g_wt [c][n][o] (contiguous chunks
// of 8 c-rows are then a single coalesced SMEM copy in the main kernel)
// ---------------------------------------------------------------------------
__global__ void k_wt(const float* __restrict__ w_conv) {
    int idx = blockIdx.x * 256 + threadIdx.x;      // 65536 total
    int nn = idx & 7;
    int c  = (idx >> 3) & 63;
    int o  = idx >> 9;
    g_wt[(c*NP_ + nn)*OUTC_ + o] = w_conv[idx];
}

// ---------------------------------------------------------------------------
// Kernel 1: offset = conv3d(x, w_p, pad=1) + b_p  -> g_offset (2,24,12,48,48)
// One block per (b,d,h) row: 24 oc x 48 w outputs.
// blockDim = 288: thread = (w = tid%48, ocg = tid/48 in 0..5), 4 oc each.
// ---------------------------------------------------------------------------
__global__ void __launch_bounds__(288) k_offset_conv(
    const float* __restrict__ x,
    const float* __restrict__ w_p,
    const float* __restrict__ b_p)
{
    __shared__ float x_s[8*3*3*50];     // [c8][dz3][dh3][w50]  (14.4 KB)
    __shared__ float w_s[8*27*24];      // [c8][k27][oc24]      (20.7 KB)

    const int bid = blockIdx.x;
    const int h = bid % H_;
    const int d = (bid / H_) % D_;
    const int b = bid / (H_*D_);
    const int tid = threadIdx.x;
    const int w   = tid % 48;
    const int ocg = tid / 48;           // 0..5

    float acc0 = __ldg(&b_p[ocg*4+0]);
    float acc1 = __ldg(&b_p[ocg*4+1]);
    float acc2 = __ldg(&b_p[ocg*4+2]);
    float acc3 = __ldg(&b_p[ocg*4+3]);

    for (int cc = 0; cc < 8; cc++) {
        const int c0 = cc * 8;
        __syncthreads();
        // stage x tile (zero-padded)
        for (int idx = tid; idx < 3600; idx += 288) {
            int wl = idx % 50; int r = idx / 50;
            int dh = r % 3; r /= 3;
            int dz = r % 3; int c = r / 3;
            int gd = d + dz - 1, gh = h + dh - 1, gw = wl - 1;
            float v = 0.f;
            if ((unsigned)gd < (unsigned)D_ && (unsigned)gh < (unsigned)H_ &&
                (unsigned)gw < (unsigned)W_)
                v = x[((b*INC_ + c0 + c)*D_ + gd)*HW_ + gh*W_ + gw];
            x_s[idx] = v;
        }
        // stage weights for this channel chunk, layout [c][k][oc]
        for (int idx = tid; idx < 5184; idx += 288) {
            int k  = idx % 27;
            int oc = (idx / 27) % 24;
            int c  = idx / (27*24);
            w_s[c*648 + k*24 + oc] = w_p[(oc*INC_ + c0 + c)*27 + k];
        }
        __syncthreads();

        #pragma unroll
        for (int c = 0; c < 8; c++) {
            #pragma unroll
            for (int kz = 0; kz < 3; kz++)
            #pragma unroll
            for (int kx = 0; kx < 3; kx++)
            #pragma unroll
            for (int ky = 0; ky < 3; ky++) {
                float xv = x_s[((c*3 + kz)*3 + kx)*50 + w + ky];
                const float4 wv = *reinterpret_cast<const float4*>(
                    &w_s[c*648 + (kz*9 + kx*3 + ky)*24 + ocg*4]);
                acc0 += xv * wv.x;
                acc1 += xv * wv.y;
                acc2 += xv * wv.z;
                acc3 += xv * wv.w;
            }
        }
    }

    const int obase = ((b*OFFC_ + ocg*4)*D_ + d)*HW_ + h*W_ + w;
    g_offset[obase              ] = acc0;
    g_offset[obase +     DHW_   ] = acc1;
    g_offset[obase + 2 * DHW_   ] = acc2;
    g_offset[obase + 3 * DHW_   ] = acc3;
}

// ---------------------------------------------------------------------------
// Kernel 2: fused deformable gather + 1x1xN conv -> g_out (2,128,12,48,48)
// One block per (b,d,h) row. blockDim = 384:
//   gather phase: thread = (n = tid/48, w = tid%48)   (exactly 384 work items)
//   gemm  phase : thread = (og = tid/48, w = tid%48), 16 oc accumulators
// ---------------------------------------------------------------------------
__global__ void __launch_bounds__(384) k_main(const float* __restrict__ x)
{
    __shared__ float xoff_s[8*8*48];    // [c8][n8][w48]   12 KB
    __shared__ float wt_s[8*8*128];     // [c8][n8][o128]  32 KB

    const int bid = blockIdx.x;
    const int h = bid % H_;
    const int d = (bid / H_) % D_;
    const int b = bid / (H_*D_);
    const int tid = threadIdx.x;
    const int w  = tid % 48;
    const int n  = tid / 48;            // gather role
    const int og = tid / 48;            // gemm role (16 oc per group)

    // ---- Phase A: per-(n,w) sample indices + weights (registers) ----
    const int off_base = ((b*OFFC_)*D_ + d)*HW_ + h*W_ + w;
    const float oz = g_offset[off_base + (n       )*DHW_];
    const float ox = g_offset[off_base + (NP_  + n)*DHW_];
    const float oy = g_offset[off_base + (2*NP_+ n)*DHW_];

    const float pz = oz + (float)d + c_pnz[n];
    const float px = ox + (float)h + c_pnx[n];
    const float py = oy + (float)w + c_pny[n];

    const float fz = floorf(pz), fx = floorf(px), fy = floorf(py);
    const float z0f = fminf(fmaxf(fz,       0.f), (float)(D_-1));
    const float z1f = fminf(fmaxf(fz + 1.f, 0.f), (float)(D_-1));
    const float x0f = fminf(fmaxf(fx,       0.f), (float)(H_-1));
    const float x1f = fminf(fmaxf(fx + 1.f, 0.f), (float)(H_-1));
    const float y0f = fminf(fmaxf(fy,       0.f), (float)(W_-1));
    const float y1f = fminf(fmaxf(fy + 1.f, 0.f), (float)(W_-1));
    const float pzc = fminf(fmaxf(pz, 0.f), (float)(D_-1));
    const float pxc = fminf(fmaxf(px, 0.f), (float)(H_-1));
    const float pyc = fminf(fmaxf(py, 0.f), (float)(W_-1));

    const float az = 1.f + (z0f - pzc), bz = 1.f - (z1f - pzc);
    const float ax = 1.f + (x0f - pxc), bx = 1.f - (x1f - pxc);
    const float ay = 1.f + (y0f - pyc), by = 1.f - (y1f - pyc);

    const float g0 = az*ax*ay;   // lt  (z0,x0,y0)
    const float g1 = bz*bx*by;   // rb  (z1,x1,y1)
    const float g2 = az*bx*ay;   // lb  (z0,x1,y0)
    const float g3 = bz*ax*by;   // rt  (z1,x0,y1)

    const int z0 = (int)z0f, z1 = (int)z1f;
    const int x0 = (int)x0f, x1 = (int)x1f;
    const int y0 = (int)y0f, y1 = (int)y1f;
    const int i0 = z0*HW_ + x0*W_ + y0;
    const int i1 = z1*HW_ + x1*W_ + y1;
    const int i2 = z0*HW_ + x1*W_ + y0;
    const int i3 = z1*HW_ + x0*W_ + y1;

    float acc[16];
    #pragma unroll
    for (int j = 0; j < 16; j++) acc[j] = 0.f;

    const float* xb_base = x + b*INC_*DHW_;

    for (int cc = 0; cc < 8; cc++) {
        __syncthreads();
        // stage weight chunk (coalesced, contiguous)
        {
            const float4* src = reinterpret_cast<const float4*>(g_wt + cc*8192);
            float4* dst = reinterpret_cast<float4*>(wt_s);
            for (int i = tid; i < 2048; i += 384) dst[i] = src[i];
        }
        // gather x_off for this channel chunk
        #pragma unroll
        for (int c = 0; c < 8; c++) {
            const float* xb = xb_base + (cc*8 + c)*DHW_;
            float v = g0*__ldg(xb+i0) + g1*__ldg(xb+i1)
                    + g2*__ldg(xb+i2) + g3*__ldg(xb+i3);
            xoff_s[(c*8 + n)*48 + w] = v;
        }
        __syncthreads();
        // gemm: acc[o] += xoff[c][n][w] * wt[c][n][o]
        #pragma unroll
        for (int c = 0; c < 8; c++) {
            #pragma unroll
            for (int nn = 0; nn < 8; nn++) {
                const float xv = xoff_s[(c*8 + nn)*48 + w];
                const float4* wp = reinterpret_cast<const float4*>(
                    &wt_s[(c*8 + nn)*128 + og*16]);
                const float4 w0 = wp[0], w1 = wp[1], w2 = wp[2], w3 = wp[3];
                acc[ 0] += xv*w0.x; acc[ 1] += xv*w0.y;
                acc[ 2] += xv*w0.z; acc[ 3] += xv*w0.w;
                acc[ 4] += xv*w1.x; acc[ 5] += xv*w1.y;
                acc[ 6] += xv*w1.z; acc[ 7] += xv*w1.w;
                acc[ 8] += xv*w2.x; acc[ 9] += xv*w2.y;
                acc[10] += xv*w2.z; acc[11] += xv*w2.w;
                acc[12] += xv*w3.x; acc[13] += xv*w3.y;
                acc[14] += xv*w3.z; acc[15] += xv*w3.w;
            }
        }
    }

    #pragma unroll
    for (int j = 0; j < 16; j++) {
        int o = og*16 + j;
        g_out[((b*OUTC_ + o)*D_ + d)*HW_ + h*W_ + w] = acc[j];
    }
}

// ---------------------------------------------------------------------------
// Kernel 3a: per-channel batch statistics over (b, d, h, w)
// ---------------------------------------------------------------------------
__global__ void __launch_bounds__(256) k_stats()
{
    const int o = blockIdx.x;           // 128
    float s = 0.f, s2 = 0.f;
    for (int b = 0; b < B_; b++) {
        const float* p = g_out + (b*OUTC_ + o)*DHW_;
        for (int i = threadIdx.x; i < DHW_; i += 256) {
            float v = p[i];
            s += v; s2 += v*v;
        }
    }
    __shared__ float sh[256], sh2[256];
    sh[threadIdx.x] = s; sh2[threadIdx.x] = s2;
    __syncthreads();
    for (int st = 128; st > 0; st >>= 1) {
        if (threadIdx.x < st) {
            sh[threadIdx.x]  += sh[threadIdx.x + st];
            sh2[threadIdx.x] += sh2[threadIdx.x + st];
        }
        __syncthreads();
    }
    if (threadIdx.x == 0) {
        float mean = sh[0] / (float)REDN_;
        float var  = sh2[0] / (float)REDN_ - mean*mean;
        g_mean[o] = mean;
        g_rstd[o] = rsqrtf(var + 1e-5f);
    }
}

// ---------------------------------------------------------------------------
// Kernel 3b: BN affine + SiLU -> d_out
// ---------------------------------------------------------------------------
__global__ void __launch_bounds__(256) k_bn_silu(
    const float* __restrict__ gamma,
    const float* __restrict__ beta,
    float* __restrict__ out)
{
    const int idx = blockIdx.x * 256 + threadIdx.x;   // exactly 7,077,888
    const int o = (idx / DHW_) & (OUTC_ - 1);
    const float v = g_out[idx];
    const float y = (v - g_mean[o]) * g_rstd[o] * __ldg(&gamma[o]) + __ldg(&beta[o]);
    out[idx] = y / (1.f + __expf(-y));
}

// ---------------------------------------------------------------------------
extern "C" void kernel_launch(void* const* d_in, const int* in_sizes, int n_in,
                              void* d_out, int out_size)
{
    const float* x      = (const float*)d_in[0];
    const float* w_p    = (const float*)d_in[1];
    const float* b_p    = (const float*)d_in[2];
    const float* w_conv = (const float*)d_in[3];
    const float* gamma  = (const float*)d_in[4];
    const float* beta   = (const float*)d_in[5];
    float* out = (float*)d_out;

    k_wt<<<INC_*NP_*OUTC_/256, 256>>>(w_conv);                 // 256 blocks
    k_offset_conv<<<B_*D_*H_, 288>>>(x, w_p, b_p);             // 1152 blocks
    k_main<<<B_*D_*H_, 384>>>(x);                              // 1152 blocks
    k_stats<<<OUTC_, 256>>>();                                 // 128 blocks
    k_bn_silu<<<B_*OUTC_*DHW_/256, 256>>>(gamma, beta, out);   // 27648 blocks
}

// round 2
// speedup vs baseline: 1.4027x; 1.4027x over previous
#include <cuda_runtime.h>
#include <cuda_bf16.h>

// Problem constants
#define B_   2
#define INC_ 64
#define OUTC_ 128
#define NP_  8
#define D_   12
#define H_   48
#define W_   48
#define HW_   (H_*W_)        // 2304
#define DHW_  (D_*HW_)       // 27648
#define OFFC_ (3*NP_)        // 24
#define REDN_ (B_*DHW_)      // 55296
#define NBLK_MAIN_ (B_*D_*H_)  // 1152

// Scratch (device globals; no allocations allowed)
__device__ float g_offset[B_*OFFC_*DHW_];    // ~5.3 MB
__device__ float g_out[B_*OUTC_*DHW_];       // ~28.3 MB
__device__ float g_wt[INC_*NP_*OUTC_];       // w_conv -> [c][n][o]
__device__ float g_xt[B_*DHW_*INC_];         // x -> channel-last [b][dhw][c]
__device__ float g_part[NBLK_MAIN_*OUTC_];   // per-block partial sums
__device__ float g_part2[NBLK_MAIN_*OUTC_];  // per-block partial sumsq
__device__ float g_mean[OUTC_];
__device__ float g_rstd[OUTC_];

// _p_n(8): base=3, dep=2, row=1, mod=2
__device__ __constant__ float c_pnz[8] = {0,0,0,1,1,1,2,2};
__device__ __constant__ float c_pnx[8] = {0,0,0,0,0,0,1,1};
__device__ __constant__ float c_pny[8] = {0,1,2,0,1,2,0,1};

// ---------------- f32x2 helpers (FFMA2 path, fp32-exact) ----------------
typedef unsigned long long u64;

__device__ __forceinline__ void ffma2(u64 &d, u64 a, u64 b) {
    asm("fma.rn.f32x2 %0, %1, %2, %0;" : "+l"(d) : "l"(a), "l"(b));
}
__device__ __forceinline__ u64 dup2(float x) {
    u64 r; asm("mov.b64 %0, {%1, %1};" : "=l"(r) : "f"(x)); return r;
}
__device__ __forceinline__ u64 pack2(float lo, float hi) {
    u64 r; asm("mov.b64 %0, {%1, %2};" : "=l"(r) : "f"(lo), "f"(hi)); return r;
}
__device__ __forceinline__ float lo32(u64 v){ return __uint_as_float((unsigned int)v); }
__device__ __forceinline__ float hi32(u64 v){ return __uint_as_float((unsigned int)(v >> 32)); }

// ---------------------------------------------------------------------------
// Kernel 0a: transpose w_conv [o][c][n] -> g_wt [c][n][o]
// ---------------------------------------------------------------------------
__global__ void k_wt(const float* __restrict__ w_conv) {
    int idx = blockIdx.x * 256 + threadIdx.x;      // 65536 total
    int nn = idx & 7;
    int c  = (idx >> 3) & 63;
    int o  = idx >> 9;
    g_wt[(c*NP_ + nn)*OUTC_ + o] = w_conv[idx];
}

// ---------------------------------------------------------------------------
// Kernel 0b: transpose x [b][c][dhw] -> g_xt [b][dhw][c] (channel-last)
// ---------------------------------------------------------------------------
__global__ void __launch_bounds__(256) k_xt(const float* __restrict__ x) {
    __shared__ float tile[64][65];
    const int bid = blockIdx.x;                 // 864 blocks
    const int b = bid / (DHW_/64);
    const int p0 = (bid % (DHW_/64)) * 64;
    const int tid = threadIdx.x;
    for (int idx = tid; idx < 4096; idx += 256) {
        int c = idx >> 6, p = idx & 63;
        tile[c][p] = x[(b*INC_ + c)*DHW_ + p0 + p];
    }
    __syncthreads();
    for (int idx = tid; idx < 4096; idx += 256) {
        int p = idx >> 6, c = idx & 63;
        g_xt[(b*DHW_ + p0 + p)*INC_ + c] = tile[c][p];
    }
}

// ---------------------------------------------------------------------------
// Kernel 1: offset conv (3x3x3, pad 1) with FFMA2.
// Block = (b, d, 4 h-rows). 288 threads: hh = tid/72; (ocg 0..5, wq 0..11).
// Each thread: 4 oc (2 f32x2 pairs) x 4 w.
// ---------------------------------------------------------------------------
__global__ void __launch_bounds__(288) k_offset_conv(
    const float* __restrict__ x,
    const float* __restrict__ w_p,
    const float* __restrict__ b_p)
{
    __shared__ float x_s[8*3*6*52];     // 7488 floats, w-rows padded to 52 (16B-aligned quads)
    __shared__ float w_s[8*27*24];      // 5184 floats  [c][k][oc]

    const int bid = blockIdx.x;
    const int hblk = bid % (H_/4);
    const int d = (bid / (H_/4)) % D_;
    const int b = bid / ((H_/4)*D_);
    const int h0 = hblk * 4;
    const int tid = threadIdx.x;
    const int hh  = tid / 72;           // 0..3
    const int r   = tid % 72;
    const int ocg = r / 12;             // 0..5  (4 oc each)
    const int wq  = r % 12;             // 0..11 (4 w each)

    u64 acc[2][4];
    {
        u64 p0 = pack2(__ldg(&b_p[ocg*4+0]), __ldg(&b_p[ocg*4+1]));
        u64 p1 = pack2(__ldg(&b_p[ocg*4+2]), __ldg(&b_p[ocg*4+3]));
        #pragma unroll
        for (int i = 0; i < 4; i++) { acc[0][i] = p0; acc[1][i] = p1; }
    }

    for (int cc = 0; cc < 8; cc++) {
        __syncthreads();
        // stage x tile: [c8][dz3][dh6][w52], zero-padded
        for (int idx = tid; idx < 7488; idx += 288) {
            int wl = idx % 52; int t = idx / 52;
            int dh = t % 6; t /= 6;
            int dz = t % 3; int c = t / 3;
            int gd = d + dz - 1, gh = h0 + dh - 1, gw = wl - 1;
            float v = 0.f;
            if ((unsigned)gd < (unsigned)D_ && (unsigned)gh < (unsigned)H_ &&
                (unsigned)gw < (unsigned)W_)
                v = x[((b*INC_ + cc*8 + c)*D_ + gd)*HW_ + gh*W_ + gw];
            x_s[idx] = v;
        }
        // stage weights [c][k][oc]
        for (int idx = tid; idx < 5184; idx += 288) {
            int k  = idx % 27;
            int oc = (idx / 27) % 24;
            int c  = idx / 648;
            w_s[c*648 + k*24 + oc] = w_p[(oc*INC_ + cc*8 + c)*27 + k];
        }
        __syncthreads();

        #pragma unroll 2
        for (int c = 0; c < 8; c++) {
            #pragma unroll
            for (int kz = 0; kz < 3; kz++)
            #pragma unroll
            for (int kx = 0; kx < 3; kx++) {
                const float* xb = &x_s[((c*3 + kz)*6 + hh + kx)*52 + wq*4];
                float4 xa = *reinterpret_cast<const float4*>(xb);
                float2 xc = *reinterpret_cast<const float2*>(xb + 4);
                u64 X[6] = { dup2(xa.x), dup2(xa.y), dup2(xa.z),
                             dup2(xa.w), dup2(xc.x), dup2(xc.y) };
                #pragma unroll
                for (int ky = 0; ky < 3; ky++) {
                    ulonglong2 Wv = *reinterpret_cast<const ulonglong2*>(
                        &w_s[(c*27 + kz*9 + kx*3 + ky)*24 + ocg*4]);
                    #pragma unroll
                    for (int i = 0; i < 4; i++) {
                        ffma2(acc[0][i], Wv.x, X[ky + i]);
                        ffma2(acc[1][i], Wv.y, X[ky + i]);
                    }
                }
            }
        }
    }

    const int h = h0 + hh;
    #pragma unroll
    for (int p = 0; p < 2; p++) {
        float4 vl = make_float4(lo32(acc[p][0]), lo32(acc[p][1]),
                                lo32(acc[p][2]), lo32(acc[p][3]));
        float4 vh = make_float4(hi32(acc[p][0]), hi32(acc[p][1]),
                                hi32(acc[p][2]), hi32(acc[p][3]));
        int oc0 = ocg*4 + p*2;
        *reinterpret_cast<float4*>(
            &g_offset[((b*OFFC_ + oc0    )*D_ + d)*HW_ + h*W_ + wq*4]) = vl;
        *reinterpret_cast<float4*>(
            &g_offset[((b*OFFC_ + oc0 + 1)*D_ + d)*HW_ + h*W_ + wq*4]) = vh;
    }
}

// ---------------------------------------------------------------------------
// Kernel 2: fused deformable gather (channel-last, vectorized) + 1x1xN conv
// (FFMA2 GEMM) + per-block BN partial stats.
// Block = (b,d,h) row, 192 threads.
//   gather: (n0 = tid/48 handles n0 and n0+4, w = tid%48)
//   gemm  : (ocg = tid/12: 8 oc as 4 f32x2 pairs, wq = tid%12: 4 w)
// ---------------------------------------------------------------------------
__global__ void __launch_bounds__(192) k_main()
{
    __shared__ float xoff_s[64*48];     // 12 KB   [k=c*8+n][w]
    __shared__ float wt_s[64*128];      // 32 KB   [k][oc]

    const int bid = blockIdx.x;
    const int h = bid % H_;
    const int d = (bid / H_) % D_;
    const int b = bid / (H_*D_);
    const int tid = threadIdx.x;
    const int w  = tid % 48;
    const int n0 = tid / 48;            // 0..3
    const int ocg = tid / 12;           // 0..15
    const int wq  = tid % 12;           // 0..11

    // ---- per-n gather setup (2 n's per thread) ----
    int   qidx[2][4];
    float gwt[2][4];
    const int bD = b * DHW_;
    #pragma unroll
    for (int s = 0; s < 2; s++) {
        const int n = n0 + s*4;
        const int off_base = (b*OFFC_*D_ + d)*HW_ + h*W_ + w;
        const float oz = g_offset[off_base + n*DHW_];
        const float ox = g_offset[off_base + (NP_  + n)*DHW_];
        const float oy = g_offset[off_base + (2*NP_+ n)*DHW_];

        const float pz = oz + (float)d + c_pnz[n];
        const float px = ox + (float)h + c_pnx[n];
        const float py = oy + (float)w + c_pny[n];

        const float fz = floorf(pz), fx = floorf(px), fy = floorf(py);
        const float z0f = fminf(fmaxf(fz,       0.f), (float)(D_-1));
        const float z1f = fminf(fmaxf(fz + 1.f, 0.f), (float)(D_-1));
        const float x0f = fminf(fmaxf(fx,       0.f), (float)(H_-1));
        const float x1f = fminf(fmaxf(fx + 1.f, 0.f), (float)(H_-1));
        const float y0f = fminf(fmaxf(fy,       0.f), (float)(W_-1));
        const float y1f = fminf(fmaxf(fy + 1.f, 0.f), (float)(W_-1));
        const float pzc = fminf(fmaxf(pz, 0.f), (float)(D_-1));
        const float pxc = fminf(fmaxf(px, 0.f), (float)(H_-1));
        const float pyc = fminf(fmaxf(py, 0.f), (float)(W_-1));

        const float az = 1.f + (z0f - pzc), bz = 1.f - (z1f - pzc);
        const float ax = 1.f + (x0f - pxc), bx = 1.f - (x1f - pxc);
        const float ay = 1.f + (y0f - pyc), by = 1.f - (y1f - pyc);

        gwt[s][0] = az*ax*ay;
        gwt[s][1] = bz*bx*by;
        gwt[s][2] = az*bx*ay;
        gwt[s][3] = bz*ax*by;

        const int z0 = (int)z0f, z1 = (int)z1f;
        const int x0 = (int)x0f, x1 = (int)x1f;
        const int y0 = (int)y0f, y1 = (int)y1f;
        qidx[s][0] = (bD + z0*HW_ + x0*W_ + y0)*INC_;
        qidx[s][1] = (bD + z1*HW_ + x1*W_ + y1)*INC_;
        qidx[s][2] = (bD + z0*HW_ + x1*W_ + y0)*INC_;
        qidx[s][3] = (bD + z1*HW_ + x0*W_ + y1)*INC_;
    }

    u64 acc[4][4];
    #pragma unroll
    for (int p = 0; p < 4; p++)
        #pragma unroll
        for (int i = 0; i < 4; i++) acc[p][i] = 0ull;

    for (int cc = 0; cc < 8; cc++) {
        __syncthreads();
        // stage weight chunk (8192 floats)
        {
            const float4* src = reinterpret_cast<const float4*>(g_wt + cc*8192);
            float4* dst = reinterpret_cast<float4*>(wt_s);
            for (int j = tid; j < 2048; j += 192) dst[j] = __ldg(&src[j]);
        }
        // gather 8 channels x 2 n's (vectorized over channel-last x)
        const int c8 = cc*8;
        #pragma unroll
        for (int s = 0; s < 2; s++) {
            const float* p0 = g_xt + qidx[s][0] + c8;
            const float* p1 = g_xt + qidx[s][1] + c8;
            const float* p2 = g_xt + qidx[s][2] + c8;
            const float* p3 = g_xt + qidx[s][3] + c8;
            float4 a0 = __ldg((const float4*)p0), a1 = __ldg((const float4*)(p0+4));
            float4 b0 = __ldg((const float4*)p1), b1 = __ldg((const float4*)(p1+4));
            float4 e0 = __ldg((const float4*)p2), e1 = __ldg((const float4*)(p2+4));
            float4 f0 = __ldg((const float4*)p3), f1 = __ldg((const float4*)(p3+4));
            const float g0 = gwt[s][0], g1 = gwt[s][1], g2 = gwt[s][2], g3 = gwt[s][3];
            const int n = n0 + s*4;
            xoff_s[(0*8+n)*48 + w] = g0*a0.x + g1*b0.x + g2*e0.x + g3*f0.x;
            xoff_s[(1*8+n)*48 + w] = g0*a0.y + g1*b0.y + g2*e0.y + g3*f0.y;
            xoff_s[(2*8+n)*48 + w] = g0*a0.z + g1*b0.z + g2*e0.z + g3*f0.z;
            xoff_s[(3*8+n)*48 + w] = g0*a0.w + g1*b0.w + g2*e0.w + g3*f0.w;
            xoff_s[(4*8+n)*48 + w] = g0*a1.x + g1*b1.x + g2*e1.x + g3*f1.x;
            xoff_s[(5*8+n)*48 + w] = g0*a1.y + g1*b1.y + g2*e1.y + g3*f1.y;
            xoff_s[(6*8+n)*48 + w] = g0*a1.z + g1*b1.z + g2*e1.z + g3*f1.z;
            xoff_s[(7*8+n)*48 + w] = g0*a1.w + g1*b1.w + g2*e1.w + g3*f1.w;
        }
        __syncthreads();

        // GEMM: 64 k-steps, 8 oc (4 f32x2 pairs) x 4 w per thread
        #pragma unroll 4
        for (int k = 0; k < 64; k++) {
            float4 xv = *reinterpret_cast<const float4*>(&xoff_s[k*48 + wq*4]);
            ulonglong2 w01 = *reinterpret_cast<const ulonglong2*>(&wt_s[k*128 + ocg*8]);
            ulonglong2 w23 = *reinterpret_cast<const ulonglong2*>(&wt_s[k*128 + ocg*8 + 4]);
            u64 X0 = dup2(xv.x), X1 = dup2(xv.y), X2 = dup2(xv.z), X3 = dup2(xv.w);
            ffma2(acc[0][0], w01.x, X0); ffma2(acc[0][1], w01.x, X1);
            ffma2(acc[0][2], w01.x, X2); ffma2(acc[0][3], w01.x, X3);
            ffma2(acc[1][0], w01.y, X0); ffma2(acc[1][1], w01.y, X1);
            ffma2(acc[1][2], w01.y, X2); ffma2(acc[1][3], w01.y, X3);
            ffma2(acc[2][0], w23.x, X0); ffma2(acc[2][1], w23.x, X1);
            ffma2(acc[2][2], w23.x, X2); ffma2(acc[2][3], w23.x, X3);
            ffma2(acc[3][0], w23.y, X0); ffma2(acc[3][1], w23.y, X1);
            ffma2(acc[3][2], w23.y, X2); ffma2(acc[3][3], w23.y, X3);
        }
    }

    // ---- epilogue: store conv output + per-block BN partials ----
    const int ob = ((b*OUTC_ + ocg*8)*D_ + d)*HW_ + h*W_ + wq*4;
    float sv[8], s2v[8];
    #pragma unroll
    for (int p = 0; p < 4; p++) {
        float4 vl = make_float4(lo32(acc[p][0]), lo32(acc[p][1]),
                                lo32(acc[p][2]), lo32(acc[p][3]));
        float4 vh = make_float4(hi32(acc[p][0]), hi32(acc[p][1]),
                                hi32(acc[p][2]), hi32(acc[p][3]));
        *reinterpret_cast<float4*>(&g_out[ob + (2*p    )*DHW_]) = vl;
        *reinterpret_cast<float4*>(&g_out[ob + (2*p + 1)*DHW_]) = vh;
        sv[2*p]   = vl.x + vl.y + vl.z + vl.w;
        s2v[2*p]  = vl.x*vl.x + vl.y*vl.y + vl.z*vl.z + vl.w*vl.w;
        sv[2*p+1] = vh.x + vh.y + vh.z + vh.w;
        s2v[2*p+1]= vh.x*vh.x + vh.y*vh.y + vh.z*vh.z + vh.w*vh.w;
    }
    __syncthreads();                    // xoff_s reuse as reduction scratch
    #pragma unroll
    for (int j = 0; j < 8; j++) {
        xoff_s[wq*128 + ocg*8 + j]        = sv[j];
        xoff_s[1536 + wq*128 + ocg*8 + j] = s2v[j];
    }
    __syncthreads();
    if (tid < 128) {
        float S = 0.f, S2 = 0.f;
        #pragma unroll
        for (int q = 0; q < 12; q++) {
            S  += xoff_s[q*128 + tid];
            S2 += xoff_s[1536 + q*128 + tid];
        }
        g_part [bid*OUTC_ + tid] = S;
        g_part2[bid*OUTC_ + tid] = S2;
    }
}

// ---------------------------------------------------------------------------
// Kernel 3a: reduce block partials -> mean/rstd (deterministic)
// ---------------------------------------------------------------------------
__global__ void __launch_bounds__(128) k_stats_final()
{
    const int oc = blockIdx.x;          // 128
    const int t  = threadIdx.x;         // 128
    float S = 0.f, S2 = 0.f;
    for (int i = t; i < NBLK_MAIN_; i += 128) {
        S  += g_part [i*OUTC_ + oc];
        S2 += g_part2[i*OUTC_ + oc];
    }
    __shared__ float sh[128], sh2[128];
    sh[t] = S; sh2[t] = S2;
    __syncthreads();
    for (int st = 64; st > 0; st >>= 1) {
        if (t < st) { sh[t] += sh[t + st]; sh2[t] += sh2[t + st]; }
        __syncthreads();
    }
    if (t == 0) {
        float mean = sh[0] / (float)REDN_;
        float var  = sh2[0] / (float)REDN_ - mean*mean;
        g_mean[oc] = mean;
        g_rstd[oc] = rsqrtf(var + 1e-5f);
    }
}

// ---------------------------------------------------------------------------
// Kernel 3b: BN affine + SiLU -> d_out
// ---------------------------------------------------------------------------
__global__ void __launch_bounds__(256) k_bn_silu(
    const float* __restrict__ gamma,
    const float* __restrict__ beta,
    float* __restrict__ out)
{
    const int idx = blockIdx.x * 256 + threadIdx.x;   // exactly 7,077,888
    const int o = (idx / DHW_) & (OUTC_ - 1);
    const float v = g_out[idx];
    const float y = (v - g_mean[o]) * g_rstd[o] * __ldg(&gamma[o]) + __ldg(&beta[o]);
    out[idx] = y / (1.f + __expf(-y));
}

// ---------------------------------------------------------------------------
extern "C" void kernel_launch(void* const* d_in, const int* in_sizes, int n_in,
                              void* d_out, int out_size)
{
    const float* x      = (const float*)d_in[0];
    const float* w_p    = (const float*)d_in[1];
    const float* b_p    = (const float*)d_in[2];
    const float* w_conv = (const float*)d_in[3];
    const float* gamma  = (const float*)d_in[4];
    const float* beta   = (const float*)d_in[5];
    float* out = (float*)d_out;

    k_wt<<<INC_*NP_*OUTC_/256, 256>>>(w_conv);                 // 256 blocks
    k_xt<<<B_*DHW_/64, 256>>>(x);                              // 864 blocks
    k_offset_conv<<<B_*D_*(H_/4), 288>>>(x, w_p, b_p);         // 288 blocks
    k_main<<<NBLK_MAIN_, 192>>>();                             // 1152 blocks
    k_stats_final<<<OUTC_, 128>>>();                           // 128 blocks
    k_bn_silu<<<B_*OUTC_*DHW_/256, 256>>>(gamma, beta, out);   // 27648 blocks
}

// round 4
// speedup vs baseline: 1.5422x; 1.0994x over previous
#include <cuda_runtime.h>
#include <cuda_bf16.h>

// Problem constants
#define B_   2
#define INC_ 64
#define OUTC_ 128
#define NP_  8
#define D_   12
#define H_   48
#define W_   48
#define HW_   (H_*W_)        // 2304
#define DHW_  (D_*HW_)       // 27648
#define OFFC_ (3*NP_)        // 24
#define REDN_ (B_*DHW_)      // 55296
#define POSBLK_ 128
#define NBLK_MAIN_ (B_*D_*(HW_/POSBLK_))   // 432

// Scratch (device globals; no allocations allowed)
__device__ float g_offset[B_*OFFC_*DHW_];    // ~5.3 MB
__device__ float g_out[B_*OUTC_*DHW_];       // ~28.3 MB
__device__ float g_wt[INC_*NP_*OUTC_];       // w_conv -> [n][c][o]  (n-major!)
__device__ float g_xt[B_*DHW_*INC_];         // x -> channel-last [b][dhw][c]
__device__ float g_part[NBLK_MAIN_*OUTC_];   // per-block partial sums
__device__ float g_part2[NBLK_MAIN_*OUTC_];  // per-block partial sumsq
__device__ float g_mean[OUTC_];
__device__ float g_rstd[OUTC_];

// _p_n(8): base=3, dep=2, row=1, mod=2
__device__ __constant__ float c_pnz[8] = {0,0,0,1,1,1,2,2};
__device__ __constant__ float c_pnx[8] = {0,0,0,0,0,0,1,1};
__device__ __constant__ float c_pny[8] = {0,1,2,0,1,2,0,1};

// ---------------- f32x2 helpers (FFMA2 path, fp32-exact) ----------------
typedef unsigned long long u64;

__device__ __forceinline__ void ffma2(u64 &d, u64 a, u64 b) {
    asm("fma.rn.f32x2 %0, %1, %2, %0;" : "+l"(d) : "l"(a), "l"(b));
}
__device__ __forceinline__ u64 dup2(float x) {
    u64 r; asm("mov.b64 %0, {%1, %1};" : "=l"(r) : "f"(x)); return r;
}
__device__ __forceinline__ u64 pack2(float lo, float hi) {
    u64 r; asm("mov.b64 %0, {%1, %2};" : "=l"(r) : "f"(lo), "f"(hi)); return r;
}
__device__ __forceinline__ float lo32(u64 v){ return __uint_as_float((unsigned int)v); }
__device__ __forceinline__ float hi32(u64 v){ return __uint_as_float((unsigned int)(v >> 32)); }

// ---------------------------------------------------------------------------
// Kernel 0a: transpose w_conv [o][c][n] -> g_wt [n][c][o]  (n-major K order)
// ---------------------------------------------------------------------------
__global__ void k_wt(const float* __restrict__ w_conv) {
    int idx = blockIdx.x * 256 + threadIdx.x;      // 65536 total
    int nn = idx & 7;
    int c  = (idx >> 3) & 63;
    int o  = idx >> 9;
    g_wt[(nn*INC_ + c)*OUTC_ + o] = w_conv[idx];
}

// ---------------------------------------------------------------------------
// Kernel 0b: transpose x [b][c][dhw] -> g_xt [b][dhw][c] (channel-last)
// ---------------------------------------------------------------------------
__global__ void __launch_bounds__(256) k_xt(const float* __restrict__ x) {
    __shared__ float tile[64][65];
    const int bid = blockIdx.x;                 // 864 blocks
    const int b = bid / (DHW_/64);
    const int p0 = (bid % (DHW_/64)) * 64;
    const int tid = threadIdx.x;
    for (int idx = tid; idx < 4096; idx += 256) {
        int c = idx >> 6, p = idx & 63;
        tile[c][p] = x[(b*INC_ + c)*DHW_ + p0 + p];
    }
    __syncthreads();
    for (int idx = tid; idx < 4096; idx += 256) {
        int p = idx >> 6, c = idx & 63;
        g_xt[(b*DHW_ + p0 + p)*INC_ + c] = tile[c][p];
    }
}

// ---------------------------------------------------------------------------
// Kernel 1: offset conv (3x3x3, pad 1) with FFMA2.
// ---------------------------------------------------------------------------
__global__ void __launch_bounds__(288) k_offset_conv(
    const float* __restrict__ x,
    const float* __restrict__ w_p,
    const float* __restrict__ b_p)
{
    __shared__ float x_s[8*3*6*52];
    __shared__ float w_s[8*27*24];

    const int bid = blockIdx.x;
    const int hblk = bid % (H_/4);
    const int d = (bid / (H_/4)) % D_;
    const int b = bid / ((H_/4)*D_);
    const int h0 = hblk * 4;
    const int tid = threadIdx.x;
    const int hh  = tid / 72;
    const int r   = tid % 72;
    const int ocg = r / 12;
    const int wq  = r % 12;

    u64 acc[2][4];
    {
        u64 p0 = pack2(__ldg(&b_p[ocg*4+0]), __ldg(&b_p[ocg*4+1]));
        u64 p1 = pack2(__ldg(&b_p[ocg*4+2]), __ldg(&b_p[ocg*4+3]));
        #pragma unroll
        for (int i = 0; i < 4; i++) { acc[0][i] = p0; acc[1][i] = p1; }
    }

    for (int cc = 0; cc < 8; cc++) {
        __syncthreads();
        for (int idx = tid; idx < 7488; idx += 288) {
            int wl = idx % 52; int t = idx / 52;
            int dh = t % 6; t /= 6;
            int dz = t % 3; int c = t / 3;
            int gd = d + dz - 1, gh = h0 + dh - 1, gw = wl - 1;
            float v = 0.f;
            if ((unsigned)gd < (unsigned)D_ && (unsigned)gh < (unsigned)H_ &&
                (unsigned)gw < (unsigned)W_)
                v = x[((b*INC_ + cc*8 + c)*D_ + gd)*HW_ + gh*W_ + gw];
            x_s[idx] = v;
        }
        for (int idx = tid; idx < 5184; idx += 288) {
            int k  = idx % 27;
            int oc = (idx / 27) % 24;
            int c  = idx / 648;
            w_s[c*648 + k*24 + oc] = w_p[(oc*INC_ + cc*8 + c)*27 + k];
        }
        __syncthreads();

        #pragma unroll 2
        for (int c = 0; c < 8; c++) {
            #pragma unroll
            for (int kz = 0; kz < 3; kz++)
            #pragma unroll
            for (int kx = 0; kx < 3; kx++) {
                const float* xb = &x_s[((c*3 + kz)*6 + hh + kx)*52 + wq*4];
                float4 xa = *reinterpret_cast<const float4*>(xb);
                float2 xc = *reinterpret_cast<const float2*>(xb + 4);
                u64 X[6] = { dup2(xa.x), dup2(xa.y), dup2(xa.z),
                             dup2(xa.w), dup2(xc.x), dup2(xc.y) };
                #pragma unroll
                for (int ky = 0; ky < 3; ky++) {
                    ulonglong2 Wv = *reinterpret_cast<const ulonglong2*>(
                        &w_s[(c*27 + kz*9 + kx*3 + ky)*24 + ocg*4]);
                    #pragma unroll
                    for (int i = 0; i < 4; i++) {
                        ffma2(acc[0][i], Wv.x, X[ky + i]);
                        ffma2(acc[1][i], Wv.y, X[ky + i]);
                    }
                }
            }
        }
    }

    const int h = h0 + hh;
    #pragma unroll
    for (int p = 0; p < 2; p++) {
        float4 vl = make_float4(lo32(acc[p][0]), lo32(acc[p][1]),
                                lo32(acc[p][2]), lo32(acc[p][3]));
        float4 vh = make_float4(hi32(acc[p][0]), hi32(acc[p][1]),
                                hi32(acc[p][2]), hi32(acc[p][3]));
        int oc0 = ocg*4 + p*2;
        *reinterpret_cast<float4*>(
            &g_offset[((b*OFFC_ + oc0    )*D_ + d)*HW_ + h*W_ + wq*4]) = vl;
        *reinterpret_cast<float4*>(
            &g_offset[((b*OFFC_ + oc0 + 1)*D_ + d)*HW_ + h*W_ + wq*4]) = vh;
    }
}

// ---------------------------------------------------------------------------
// Kernel 2: fused deformable gather + 1x1xN conv (FFMA2) + BN partials.
// Block = 128 positions of one (b,d) slab; 256 threads (8 warps).
// K reordered n-major: chunk nn holds all 64 channels of sample n.
// xoff rows stride 65 (conflict-free GEMM reads); gather stores are SCALAR
// (stride-65 rows are not 16B-aligned -> the R3 float4 store trapped).
// Dynamic SMEM: idx 16K + gwt 16K + xoff 33280 + w 32K = 98816 B.
// ---------------------------------------------------------------------------
__global__ void __launch_bounds__(256) k_main()
{
    extern __shared__ unsigned char smraw[];
    int*   idx_s = (int*)smraw;                          // [1024*4]
    float* gwt_s = (float*)(smraw + 16384);              // [1024*4]
    float* xoff  = (float*)(smraw + 32768);              // [128][65]
    float* wt_s  = (float*)(smraw + 32768 + 33280);      // [64][128]

    const int bid = blockIdx.x;
    const int p0   = (bid % (HW_/POSBLK_)) * POSBLK_;
    const int slab = bid / (HW_/POSBLK_);
    const int d = slab % D_;
    const int b = slab / D_;
    const int tid = threadIdx.x;
    const int lane = tid & 31;
    const int wid  = tid >> 5;

    // ---- setup: corner indices + trilinear weights for 1024 (pos,n) ----
    const int bD = b * DHW_;
    #pragma unroll
    for (int i = 0; i < 4; i++) {
        const int q = tid + 256*i;          // q = n*128 + p
        const int p = q & 127;
        const int n = q >> 7;
        const int pos = p0 + p;
        const int h = pos / W_;
        const int w = pos % W_;
        const int off_base = (b*OFFC_*D_ + d)*HW_ + pos;
        const float oz = g_offset[off_base + n*DHW_];
        const float ox = g_offset[off_base + (NP_  + n)*DHW_];
        const float oy = g_offset[off_base + (2*NP_+ n)*DHW_];

        const float pz = oz + (float)d + c_pnz[n];
        const float px = ox + (float)h + c_pnx[n];
        const float py = oy + (float)w + c_pny[n];

        const float fz = floorf(pz), fx = floorf(px), fy = floorf(py);
        const float z0f = fminf(fmaxf(fz,       0.f), (float)(D_-1));
        const float z1f = fminf(fmaxf(fz + 1.f, 0.f), (float)(D_-1));
        const float x0f = fminf(fmaxf(fx,       0.f), (float)(H_-1));
        const float x1f = fminf(fmaxf(fx + 1.f, 0.f), (float)(H_-1));
        const float y0f = fminf(fmaxf(fy,       0.f), (float)(W_-1));
        const float y1f = fminf(fmaxf(fy + 1.f, 0.f), (float)(W_-1));
        const float pzc = fminf(fmaxf(pz, 0.f), (float)(D_-1));
        const float pxc = fminf(fmaxf(px, 0.f), (float)(H_-1));
        const float pyc = fminf(fmaxf(py, 0.f), (float)(W_-1));

        const float az = 1.f + (z0f - pzc), bz = 1.f - (z1f - pzc);
        const float ax = 1.f + (x0f - pxc), bx = 1.f - (x1f - pxc);
        const float ay = 1.f + (y0f - pyc), by = 1.f - (y1f - pyc);

        const int z0 = (int)z0f, z1 = (int)z1f;
        const int x0 = (int)x0f, x1 = (int)x1f;
        const int y0 = (int)y0f, y1 = (int)y1f;

        idx_s[q*4+0] = (bD + z0*HW_ + x0*W_ + y0)*INC_;
        idx_s[q*4+1] = (bD + z1*HW_ + x1*W_ + y1)*INC_;
        idx_s[q*4+2] = (bD + z0*HW_ + x1*W_ + y0)*INC_;
        idx_s[q*4+3] = (bD + z1*HW_ + x0*W_ + y1)*INC_;
        gwt_s[q*4+0] = az*ax*ay;
        gwt_s[q*4+1] = bz*bx*by;
        gwt_s[q*4+2] = az*bx*ay;
        gwt_s[q*4+3] = bz*ax*by;
    }

    u64 acc[8][4];
    #pragma unroll
    for (int pr = 0; pr < 8; pr++)
        #pragma unroll
        for (int j = 0; j < 4; j++) acc[pr][j] = 0ull;

    const int f    = lane & 15;     // channel-quad
    const int half = lane >> 4;     // corner pair selector

    for (int nn = 0; nn < 8; nn++) {
        __syncthreads();            // protect wt_s / xoff reuse
        // stage weights for this n: g_wt[nn*64 .. ][128]
        {
            const float4* src = reinterpret_cast<const float4*>(g_wt + nn*8192);
            float4* dst = reinterpret_cast<float4*>(wt_s);
            #pragma unroll
            for (int j = 0; j < 8; j++) dst[tid + 256*j] = __ldg(&src[tid + 256*j]);
        }
        // gather: warp wid covers pos p = wid*16 .. wid*16+15
        #pragma unroll 2
        for (int pp = 0; pp < 16; pp++) {
            const int p = wid*16 + pp;
            const int q4 = ((nn << 7) + p) << 2;
            const int   i0 = idx_s[q4 + half];
            const float g0 = gwt_s[q4 + half];
            const int   i1 = idx_s[q4 + half + 2];
            const float g1 = gwt_s[q4 + half + 2];
            const float4 v0 = __ldg((const float4*)(g_xt + i0 + 4*f));
            const float4 v1 = __ldg((const float4*)(g_xt + i1 + 4*f));
            float4 rv;
            rv.x = g0*v0.x + g1*v1.x;
            rv.y = g0*v0.y + g1*v1.y;
            rv.z = g0*v0.z + g1*v1.z;
            rv.w = g0*v0.w + g1*v1.w;
            rv.x += __shfl_xor_sync(0xffffffffu, rv.x, 16);
            rv.y += __shfl_xor_sync(0xffffffffu, rv.y, 16);
            rv.z += __shfl_xor_sync(0xffffffffu, rv.z, 16);
            rv.w += __shfl_xor_sync(0xffffffffu, rv.w, 16);
            if (half == 0) {
                // scalar stores: stride-65 rows are only 4B-aligned (no STS.128)
                float* rowp = &xoff[p*65 + 4*f];
                rowp[0] = rv.x;
                rowp[1] = rv.y;
                rowp[2] = rv.z;
                rowp[3] = rv.w;
            }
        }
        __syncthreads();

        // GEMM: warp = ocg, 16 oc; lanes = pos (lane + 32j)
        const int ocg = wid;
        #pragma unroll 4
        for (int k = 0; k < 64; k++) {
            const float x0 = xoff[(lane      )*65 + k];
            const float x1 = xoff[(lane + 32 )*65 + k];
            const float x2 = xoff[(lane + 64 )*65 + k];
            const float x3 = xoff[(lane + 96 )*65 + k];
            const ulonglong2 wa = *reinterpret_cast<const ulonglong2*>(&wt_s[k*128 + ocg*16     ]);
            const ulonglong2 wb = *reinterpret_cast<const ulonglong2*>(&wt_s[k*128 + ocg*16 + 4 ]);
            const ulonglong2 wc = *reinterpret_cast<const ulonglong2*>(&wt_s[k*128 + ocg*16 + 8 ]);
            const ulonglong2 wd = *reinterpret_cast<const ulonglong2*>(&wt_s[k*128 + ocg*16 + 12]);
            const u64 X0 = dup2(x0), X1 = dup2(x1), X2 = dup2(x2), X3 = dup2(x3);
            ffma2(acc[0][0], wa.x, X0); ffma2(acc[0][1], wa.x, X1);
            ffma2(acc[0][2], wa.x, X2); ffma2(acc[0][3], wa.x, X3);
            ffma2(acc[1][0], wa.y, X0); ffma2(acc[1][1], wa.y, X1);
            ffma2(acc[1][2], wa.y, X2); ffma2(acc[1][3], wa.y, X3);
            ffma2(acc[2][0], wb.x, X0); ffma2(acc[2][1], wb.x, X1);
            ffma2(acc[2][2], wb.x, X2); ffma2(acc[2][3], wb.x, X3);
            ffma2(acc[3][0], wb.y, X0); ffma2(acc[3][1], wb.y, X1);
            ffma2(acc[3][2], wb.y, X2); ffma2(acc[3][3], wb.y, X3);
            ffma2(acc[4][0], wc.x, X0); ffma2(acc[4][1], wc.x, X1);
            ffma2(acc[4][2], wc.x, X2); ffma2(acc[4][3], wc.x, X3);
            ffma2(acc[5][0], wc.y, X0); ffma2(acc[5][1], wc.y, X1);
            ffma2(acc[5][2], wc.y, X2); ffma2(acc[5][3], wc.y, X3);
            ffma2(acc[6][0], wd.x, X0); ffma2(acc[6][1], wd.x, X1);
            ffma2(acc[6][2], wd.x, X2); ffma2(acc[6][3], wd.x, X3);
            ffma2(acc[7][0], wd.y, X0); ffma2(acc[7][1], wd.y, X1);
            ffma2(acc[7][2], wd.y, X2); ffma2(acc[7][3], wd.y, X3);
        }
    }

    // ---- epilogue: store conv out (coalesced) + warp-reduced BN partials ----
    const int ocg = wid;
    #pragma unroll
    for (int pr = 0; pr < 8; pr++) {
        const int oc0 = ocg*16 + pr*2;
        float sl = 0.f, sl2 = 0.f, sh = 0.f, sh2 = 0.f;
        #pragma unroll
        for (int j = 0; j < 4; j++) {
            const int pos = p0 + lane + 32*j;
            const float vl = lo32(acc[pr][j]);
            const float vh = hi32(acc[pr][j]);
            g_out[((b*OUTC_ + oc0    )*D_ + d)*HW_ + pos] = vl;
            g_out[((b*OUTC_ + oc0 + 1)*D_ + d)*HW_ + pos] = vh;
            sl += vl; sl2 += vl*vl;
            sh += vh; sh2 += vh*vh;
        }
        #pragma unroll
        for (int st = 16; st > 0; st >>= 1) {
            sl  += __shfl_xor_sync(0xffffffffu, sl,  st);
            sl2 += __shfl_xor_sync(0xffffffffu, sl2, st);
            sh  += __shfl_xor_sync(0xffffffffu, sh,  st);
            sh2 += __shfl_xor_sync(0xffffffffu, sh2, st);
        }
        if (lane == 0) {
            g_part [bid*OUTC_ + oc0    ] = sl;
            g_part2[bid*OUTC_ + oc0    ] = sl2;
            g_part [bid*OUTC_ + oc0 + 1] = sh;
            g_part2[bid*OUTC_ + oc0 + 1] = sh2;
        }
    }
}

// ---------------------------------------------------------------------------
// Kernel 3a: reduce block partials -> mean/rstd (deterministic)
// ---------------------------------------------------------------------------
__global__ void __launch_bounds__(128) k_stats_final()
{
    const int oc = blockIdx.x;
    const int t  = threadIdx.x;
    float S = 0.f, S2 = 0.f;
    for (int i = t; i < NBLK_MAIN_; i += 128) {
        S  += g_part [i*OUTC_ + oc];
        S2 += g_part2[i*OUTC_ + oc];
    }
    __shared__ float sh[128], sh2[128];
    sh[t] = S; sh2[t] = S2;
    __syncthreads();
    for (int st = 64; st > 0; st >>= 1) {
        if (t < st) { sh[t] += sh[t + st]; sh2[t] += sh2[t + st]; }
        __syncthreads();
    }
    if (t == 0) {
        float mean = sh[0] / (float)REDN_;
        float var  = sh2[0] / (float)REDN_ - mean*mean;
        g_mean[oc] = mean;
        g_rstd[oc] = rsqrtf(var + 1e-5f);
    }
}

// ---------------------------------------------------------------------------
// Kernel 3b: BN affine + SiLU -> d_out
// ---------------------------------------------------------------------------
__global__ void __launch_bounds__(256) k_bn_silu(
    const float* __restrict__ gamma,
    const float* __restrict__ beta,
    float* __restrict__ out)
{
    const int idx = blockIdx.x * 256 + threadIdx.x;
    const int o = (idx / DHW_) & (OUTC_ - 1);
    const float v = g_out[idx];
    const float y = (v - g_mean[o]) * g_rstd[o] * __ldg(&gamma[o]) + __ldg(&beta[o]);
    out[idx] = y / (1.f + __expf(-y));
}

// ---------------------------------------------------------------------------
extern "C" void kernel_launch(void* const* d_in, const int* in_sizes, int n_in,
                              void* d_out, int out_size)
{
    const float* x      = (const float*)d_in[0];
    const float* w_p    = (const float*)d_in[1];
    const float* b_p    = (const float*)d_in[2];
    const float* w_conv = (const float*)d_in[3];
    const float* gamma  = (const float*)d_in[4];
    const float* beta   = (const float*)d_in[5];
    float* out = (float*)d_out;

    cudaFuncSetAttribute(k_main, cudaFuncAttributeMaxDynamicSharedMemorySize, 98816);

    k_wt<<<INC_*NP_*OUTC_/256, 256>>>(w_conv);                 // 256 blocks
    k_xt<<<B_*DHW_/64, 256>>>(x);                              // 864 blocks
    k_offset_conv<<<B_*D_*(H_/4), 288>>>(x, w_p, b_p);         // 288 blocks
    k_main<<<NBLK_MAIN_, 256, 98816>>>();                      // 432 blocks
    k_stats_final<<<OUTC_, 128>>>();                           // 128 blocks
    k_bn_silu<<<B_*OUTC_*DHW_/256, 256>>>(gamma, beta, out);   // 27648 blocks
}